// round 16
// baseline (speedup 1.0000x reference)
#include <cuda_runtime.h>
#include <cuda_fp16.h>
#include <cstdint>

#define BB 8
#define SS 2048
#define DD 512
#define CC 1024
#define NROW (BB*SS)   // 16384

// ---------------------------------------------------------------------------
// Scratch (device globals)
// ---------------------------------------------------------------------------
__device__ unsigned short g_Xb[(size_t)NROW*DD], g_Yb[(size_t)NROW*DD];
__device__ unsigned short g_Wxqb[DD*DD], g_Wyqb[DD*DD];
__device__ unsigned short g_Wfkb[DD*CC], g_Wfvb[DD*CC];
__device__ unsigned short g_Qb[(size_t)NROW*CC];      // [row, 1024] = Q1|Q2
__device__ unsigned short g_Kb[(size_t)NROW*DD];
__device__ unsigned short g_Vtb[(size_t)BB*DD*SS];    // [b, d, s]
__device__ unsigned short g_Pb1[(size_t)BB*SS*SS];    // fp16 unnormalized exp(scores)
__device__ unsigned short g_Pb2[(size_t)BB*SS*SS];
__device__ float          g_rinv1[NROW], g_rinv2[NROW];

// ---------------------------------------------------------------------------
// Helpers
// ---------------------------------------------------------------------------
__device__ __forceinline__ uint32_t smem_u32(const void* p) {
    uint32_t a;
    asm("{ .reg .u64 t; cvta.to.shared.u64 t, %1; cvt.u32.u64 %0, t; }"
        : "=r"(a) : "l"(p));
    return a;
}
__device__ __forceinline__ void cp16(uint32_t s, const void* g) {
    asm volatile("cp.async.cg.shared.global [%0], [%1], 16;" :: "r"(s), "l"(g));
}
#define CP_COMMIT() asm volatile("cp.async.commit_group;" ::: "memory")
#define CP_WAIT0()  asm volatile("cp.async.wait_group 0;" ::: "memory")

__device__ __forceinline__ void ldm_x4(uint32_t* r, uint32_t a) {
    asm volatile("ldmatrix.sync.aligned.m8n8.x4.shared.b16 {%0,%1,%2,%3}, [%4];"
        : "=r"(r[0]), "=r"(r[1]), "=r"(r[2]), "=r"(r[3]) : "r"(a));
}
__device__ __forceinline__ void mma_f16(uint32_t* d, const uint32_t* a, const uint32_t* b) {
    asm volatile(
        "mma.sync.aligned.m16n8k16.row.col.f16.f16.f16.f16 "
        "{%0,%1}, {%2,%3,%4,%5}, {%6,%7}, {%0,%1};"
        : "+r"(d[0]), "+r"(d[1])
        : "r"(a[0]), "r"(a[1]), "r"(a[2]), "r"(a[3]), "r"(b[0]), "r"(b[1]));
}
__device__ __forceinline__ unsigned short f2h(float v) {
    return __half_as_ushort(__float2half_rn(v));
}

// ---------------------------------------------------------------------------
// SMEM: 2 stages x (A 128x64 | B 128x64) fp16, row stride 144B.
// 72KB per CTA -> THREE CTAs co-resident per SM.
// ---------------------------------------------------------------------------
#define STAGES     2
#define ROWB       144
#define A_TILE_B   (128 * ROWB)
#define B_TILE_B   (128 * ROWB)
#define STAGE_B    (A_TILE_B + B_TILE_B)      // 36864
#define SMEM_TOTAL (STAGES * STAGE_B)         // 73728

// ---------------------------------------------------------------------------
// Single-pass fp16 TN GEMM (fp16 acc), CTA tile 128x128, 256 thr
// (8 warps 2x4, warp tile 64x32, ~80 regs), k-chunk 64, double-buffered,
// 3 CTAs/SM.
//
// mode 1: Ch[m*ld+n] = f16(acc + bias[n])
// mode 2: Ch[n*ld+m] = f16(acc + bias[n])   (transposed)
// mode 6: Ch[m*ld+n] = f16(exp2(alpha*acc))          (QK + exp epilogue)
// mode 7: Cf[m*ld+n] = acc*rinv[row] + add1? + add2? (+Cf if accumulate)
//         (bias ptr = rinv, indexed by row bz*2048+m)
// ---------------------------------------------------------------------------
__global__ __launch_bounds__(256, 3) void hmma_tn(
    const unsigned short* __restrict__ A, const unsigned short* __restrict__ Aseg2,
    int KA, const unsigned short* __restrict__ B, int bmask,
    int K, int lda, int ldb, long long a_bs, long long b_bs,
    int zsplit,
    int mode, float alpha, const float* __restrict__ bias,
    float* __restrict__ Cf, unsigned short* __restrict__ Cb,
    long long c_bs, int c_ld,
    const float* __restrict__ add1, const float* __restrict__ add2,
    const unsigned short* __restrict__ A_alt, const unsigned short* __restrict__ B_alt,
    const float* __restrict__ bias_alt, unsigned short* __restrict__ Cb_alt,
    long long cbs_alt, int cld_alt, int mode_alt)
{
    extern __shared__ char smem[];
    const uint32_t sbase = smem_u32(smem);

    const int tid  = threadIdx.x;
    const int wid  = tid >> 5;
    const int lane = tid & 31;
    const int warpM = wid >> 2;      // 0..1 (64 rows each)
    const int warpN = wid & 3;       // 0..3 (32 cols each)
    int bz = blockIdx.z;
    const int bm = blockIdx.y * 128, bn = blockIdx.x * 128;

    // operand-set select
    const unsigned short* Ab = A;
    const unsigned short* Bb = B;
    const float* biasp = bias;
    unsigned short* Cbp = Cb;
    long long cbs = c_bs;
    int cld = c_ld;
    int md = mode;
    if (zsplit > 0 && bz >= zsplit) {
        bz -= zsplit;
        Ab = A_alt; Bb = B_alt; biasp = bias_alt;
        Cbp = Cb_alt; cbs = cbs_alt; cld = cld_alt; md = mode_alt;
    }

    const unsigned short* gA1 = Ab + bz * a_bs + (long long)bm * lda;
    const unsigned short* gA2 =
        Aseg2 ? Aseg2 + bz * a_bs + (long long)bm * lda : nullptr;
    const unsigned short* gB = Bb + bz * b_bs + (long long)bn * ldb;

    uint32_t acc[4][4][2];
#pragma unroll
    for (int i = 0; i < 4; ++i)
#pragma unroll
        for (int j = 0; j < 4; ++j) { acc[i][j][0] = 0u; acc[i][j][1] = 0u; }

    const int nch = K >> 6;   // k-chunks of 64

    const int lr = tid >> 3, lc = tid & 7;   // 32 rows x 8 segs per pass
#define LOAD_CHUNK(c)                                                        \
    do {                                                                     \
        const int koff_ = (c) * 64;                                          \
        const unsigned short* gAc_ = gA1; int ka_ = koff_;                   \
        if (gA2 && koff_ >= KA) { gAc_ = gA2; ka_ = koff_ - KA; }            \
        const int kb_ = koff_ & bmask;                                       \
        const uint32_t sb_ = sbase + ((c) & 1) * STAGE_B;                    \
        _Pragma("unroll")                                                    \
        for (int h_ = 0; h_ < 4; ++h_) {      /* A: 128 rows */              \
            const int row_ = lr + h_ * 32;                                   \
            cp16(sb_ + (uint32_t)(row_ * ROWB + lc * 16),                    \
                 gAc_ + (long long)row_ * lda + ka_ + lc * 8);               \
        }                                                                    \
        _Pragma("unroll")                                                    \
        for (int h_ = 0; h_ < 4; ++h_) {      /* B: 128 rows */              \
            const int row_ = lr + h_ * 32;                                   \
            cp16(sb_ + A_TILE_B + (uint32_t)(row_ * ROWB + lc * 16),         \
                 gB + (long long)row_ * ldb + kb_ + lc * 8);                 \
        }                                                                    \
        CP_COMMIT();                                                         \
    } while (0)

    LOAD_CHUNK(0);

    // ldmatrix geometry
    const int a_row = warpM * 64 + (lane & 15);
    const int a_colb = (lane >> 4) * 16;
    const int b_row = warpN * 32 + (lane & 7) + ((lane >> 4) & 1) * 8;
    const int b_colb = ((lane >> 3) & 1) * 16;

    for (int c = 0; c < nch; ++c) {
        CP_WAIT0();
        __syncthreads();

        if (c + 1 < nch) LOAD_CHUNK(c + 1);

        const uint32_t tA = sbase + (c & 1) * STAGE_B;
        const uint32_t tB = tA + A_TILE_B;

#pragma unroll
        for (int ks = 0; ks < 4; ++ks) {
            uint32_t af[4][4], bfr[4][2];
#pragma unroll
            for (int mi = 0; mi < 4; ++mi)
                ldm_x4(af[mi], tA + (uint32_t)((a_row + mi * 16) * ROWB
                                               + ks * 32 + a_colb));
#pragma unroll
            for (int p = 0; p < 2; ++p) {
                uint32_t r[4];
                ldm_x4(r, tB + (uint32_t)((b_row + p * 16) * ROWB
                                          + ks * 32 + b_colb));
                bfr[2*p][0] = r[0]; bfr[2*p][1] = r[1];
                bfr[2*p+1][0] = r[2]; bfr[2*p+1][1] = r[3];
            }
#pragma unroll
            for (int mi = 0; mi < 4; ++mi)
#pragma unroll
                for (int ni = 0; ni < 4; ++ni)
                    mma_f16(acc[mi][ni], af[mi], bfr[ni]);
        }
    }
#undef LOAD_CHUNK

    // ------------------------- epilogue (register direct) -------------------
    const int g = lane >> 2, tig = lane & 3;
    const long long c_off = (long long)bz * cbs;

    // mode 7: per-row scales (8 distinct rows per thread), hoisted
    float rm[4][2];
    if (md == 7) {
#pragma unroll
        for (int mi = 0; mi < 4; ++mi)
#pragma unroll
            for (int half = 0; half < 2; ++half)
                rm[mi][half] = __ldg(biasp + (long long)bz * 2048
                                     + bm + warpM * 64 + mi * 16 + g + half * 8);
    }

#pragma unroll
    for (int mi = 0; mi < 4; ++mi) {
#pragma unroll
        for (int ni = 0; ni < 4; ++ni) {
            const int m0 = bm + warpM * 64 + mi * 16 + g;
            const int n0 = bn + warpN * 32 + ni * 8 + tig * 2;
#pragma unroll
            for (int half = 0; half < 2; ++half) {
                const int m = m0 + half * 8;
                const __half2 hv = *(const __half2*)&acc[mi][ni][half];
                float v0 = __low2float(hv);
                float v1 = __high2float(hv);
                if (md == 6) {
                    *(ushort2*)&Cbp[c_off + (long long)m * cld + n0] =
                        make_ushort2(f2h(exp2f(alpha * v0)),
                                     f2h(exp2f(alpha * v1)));
                } else if (md == 1) {
                    v0 += __ldg(biasp + n0);
                    v1 += __ldg(biasp + n0 + 1);
                    *(ushort2*)&Cbp[c_off + (long long)m * cld + n0] =
                        make_ushort2(f2h(v0), f2h(v1));
                } else if (md == 2) {
                    v0 += __ldg(biasp + n0);
                    v1 += __ldg(biasp + n0 + 1);
                    Cbp[c_off + (long long)n0 * cld + m] = f2h(v0);
                    Cbp[c_off + (long long)(n0 + 1) * cld + m] = f2h(v1);
                } else {  // mode 7
                    const float r = rm[mi][half];
                    v0 *= r; v1 *= r;
                    const long long o = c_off + (long long)m * cld + n0;
                    if (add1) { float2 t = *(const float2*)&add1[o]; v0 += t.x; v1 += t.y; }
                    if (add2) { float2 t = *(const float2*)&add2[o]; v0 += t.x; v1 += t.y; }
                    if (Cf != add1 && Cf != add2 && !add1 && !add2) { /* no-op */ }
                    if (alpha < 0.f) { float2 t = *(const float2*)&Cf[o]; v0 += t.x; v1 += t.y; }
                    *(float2*)&Cf[o] = make_float2(v0, v1);
                }
            }
        }
    }
}

// ---------------------------------------------------------------------------
// fp32 -> fp16, vectorized: two equal-size arrays in one launch
// ---------------------------------------------------------------------------
__global__ __launch_bounds__(256) void tofp16_dual(
    const float* __restrict__ s1, unsigned short* __restrict__ d1,
    const float* __restrict__ s2, unsigned short* __restrict__ d2, int n)
{
    const int q = n >> 2;
    const int i = blockIdx.x * 256 + threadIdx.x;
    const float* s;
    unsigned short* d;
    int j;
    if (i < q)           { s = s1; d = d1; j = i; }
    else if (i < 2 * q)  { s = s2; d = d2; j = i - q; }
    else return;
    const float4 v = *(const float4*)(s + (size_t)j * 4);
    ushort4 o;
    o.x = f2h(v.x); o.y = f2h(v.y); o.z = f2h(v.z); o.w = f2h(v.w);
    *(ushort4*)(d + (size_t)j * 4) = o;
}

// ---------------------------------------------------------------------------
// Row-sum reciprocal over unnormalized exp rows (rows of 2048, fp16).
// One block per row, coalesced uint4 reads, rinv[row] = 1/sum (fp32).
// ---------------------------------------------------------------------------
__global__ __launch_bounds__(256) void rowsum_recip(
    const unsigned short* __restrict__ P1, const unsigned short* __restrict__ P2,
    float* __restrict__ r1, float* __restrict__ r2)
{
    const unsigned short* Pb;
    float* rp;
    int b = blockIdx.x;
    if (b < NROW) { Pb = P1; rp = r1; }
    else          { Pb = P2; rp = r2; b -= NROW; }
    const uint4* row = (const uint4*)(Pb + (long long)b * 2048);
    const int t = threadIdx.x;
    __shared__ float red[8];

    const uint4 pk = row[t];
    const __half2* h = (const __half2*)&pk;
    float s = 0.f;
#pragma unroll
    for (int i = 0; i < 4; ++i) {
        const float2 f = __half22float2(h[i]);
        s += f.x + f.y;
    }
#pragma unroll
    for (int o = 16; o > 0; o >>= 1) s += __shfl_xor_sync(0xffffffffu, s, o);
    if ((t & 31) == 0) red[t >> 5] = s;
    __syncthreads();
    if (t == 0) {
        float tot = red[0];
#pragma unroll
        for (int w = 1; w < 8; ++w) tot += red[w];
        rp[b] = 1.0f / tot;
    }
}

// ---------------------------------------------------------------------------
// Launch sequence
// ---------------------------------------------------------------------------
extern "C" void kernel_launch(void* const* d_in, const int* in_sizes, int n_in,
                              void* d_out, int out_size)
{
    (void)in_sizes; (void)n_in; (void)out_size;

    const float* X    = (const float*)d_in[0];
    const float* Y    = (const float*)d_in[1];
    const float* W_xq = (const float*)d_in[2];
    const float* b_xq = (const float*)d_in[3];
    const float* W_yq = (const float*)d_in[4];
    const float* b_yq = (const float*)d_in[5];
    const float* W_fk = (const float*)d_in[6];
    const float* b_fk = (const float*)d_in[7];
    const float* W_fv = (const float*)d_in[8];
    const float* b_fv = (const float*)d_in[9];
    float* out = (float*)d_out;

#define SYM(T, name, gsym) T* name; cudaGetSymbolAddress((void**)&name, gsym)
    SYM(unsigned short, Xb, g_Xb);     SYM(unsigned short, Yb, g_Yb);
    SYM(unsigned short, Wxqb, g_Wxqb); SYM(unsigned short, Wyqb, g_Wyqb);
    SYM(unsigned short, Wfkb, g_Wfkb); SYM(unsigned short, Wfvb, g_Wfvb);
    SYM(unsigned short, Qb, g_Qb);     SYM(unsigned short, Kb, g_Kb);
    SYM(unsigned short, Vtb, g_Vtb);
    SYM(unsigned short, Pb1, g_Pb1);   SYM(unsigned short, Pb2, g_Pb2);
    SYM(float, rinv1, g_rinv1);        SYM(float, rinv2, g_rinv2);
#undef SYM

    cudaFuncSetAttribute(hmma_tn, cudaFuncAttributeMaxDynamicSharedMemorySize, SMEM_TOTAL);

    // alpha for QK: (1/sqrt(512)) * log2(e), so exp2(alpha*acc) = exp(scale*acc)
    const float alpha_qk = 0.06375948809f;
    const long long XBS = (long long)SS * DD;
    const long long QBS = (long long)SS * CC;
    const long long PBS = (long long)SS * SS;
    const long long VBS = (long long)DD * SS;

    // ---- fp16 conversions ----
    const int nX = NROW * DD;
    tofp16_dual<<<(2 * (nX / 4)) / 256, 256>>>(X, Xb, Y, Yb, nX);
    tofp16_dual<<<(2 * (DD * DD / 4)) / 256, 256>>>(W_xq, Wxqb, W_yq, Wyqb, DD * DD);
    tofp16_dual<<<(2 * (DD * CC / 4)) / 256, 256>>>(W_fk, Wfkb, W_fv, Wfvb, DD * CC);

    // ---- projections: Q1 (z<8) and Q2 (z>=8) in one launch ----
    hmma_tn<<<dim3(4, 16, 16), 256, SMEM_TOTAL>>>(
        Xb, nullptr, DD, Wxqb, DD - 1,
        DD, DD, DD, XBS, 0, /*zsplit*/8,
        1, 1.f, b_xq, nullptr, Qb, QBS, CC, nullptr, nullptr,
        Yb, Wyqb, b_yq, Qb + DD, QBS, CC, 1);

    // ---- Kf (z<8, mode 1) and Vt (z>=8, mode 2 transposed) ----
    hmma_tn<<<dim3(4, 16, 16), 256, SMEM_TOTAL>>>(
        Qb, nullptr, CC, Wfkb, CC - 1,
        CC, CC, CC, QBS, 0, /*zsplit*/8,
        1, 1.f, b_fk, nullptr, Kb, XBS, DD, nullptr, nullptr,
        Qb, Wfvb, b_fv, Vtb, VBS, SS, 2);

    // ---- QK with fused exp: E1 -> Pb1 (z<8), E2 -> Pb2 (z>=8) ----
    hmma_tn<<<dim3(16, 16, 16), 256, SMEM_TOTAL>>>(
        Qb, nullptr, DD, Kb, DD - 1,
        DD, CC, DD, QBS, XBS, /*zsplit*/8,
        6, alpha_qk, nullptr, nullptr, Pb1, PBS, SS, nullptr, nullptr,
        Qb + DD, Kb, nullptr, Pb2, PBS, SS, 6);

    // ---- row sums -> reciprocals (deterministic, read-only over E) ----
    rowsum_recip<<<2 * NROW, 256>>>(Pb1, Pb2, rinv1, rinv2);

    // ---- PV1: out = rinv1[m]*(E1@Vt^T) + X + Y   (alpha>=0: no accumulate) ----
    hmma_tn<<<dim3(4, 16, 8), 256, SMEM_TOTAL>>>(
        Pb1, nullptr, SS, Vtb, SS - 1,
        SS, SS, SS, PBS, VBS, /*zsplit*/0,
        7, 1.f, rinv1, out, nullptr, XBS, DD, X, Y,
        nullptr, nullptr, nullptr, nullptr, 0, 0, 0);

    // ---- PV2: out += rinv2[m]*(E2@Vt^T)   (alpha<0 signals accumulate) ----
    hmma_tn<<<dim3(4, 16, 8), 256, SMEM_TOTAL>>>(
        Pb2, nullptr, SS, Vtb, SS - 1,
        SS, SS, SS, PBS, VBS, /*zsplit*/0,
        7, -1.f, rinv2, out, nullptr, XBS, DD, nullptr, nullptr,
        nullptr, nullptr, nullptr, nullptr, 0, 0, 0);
}

// round 17
// speedup vs baseline: 1.0862x; 1.0862x over previous
#include <cuda_runtime.h>
#include <cuda_fp16.h>
#include <cstdint>

#define BB 8
#define SS 2048
#define DD 512
#define CC 1024
#define NROW (BB*SS)   // 16384

// ---------------------------------------------------------------------------
// Scratch (device globals)
// ---------------------------------------------------------------------------
__device__ unsigned short g_Xb[(size_t)NROW*DD], g_Yb[(size_t)NROW*DD];
__device__ unsigned short g_Wxqb[DD*DD], g_Wyqb[DD*DD];
__device__ unsigned short g_Wfkb[DD*CC], g_Wfvb[DD*CC];
__device__ unsigned short g_Qb[(size_t)NROW*CC];      // [row, 1024] = Q1|Q2
__device__ unsigned short g_Kb[(size_t)NROW*DD];
__device__ unsigned short g_Vtb[(size_t)BB*DD*SS];    // [b, d, s]
__device__ unsigned short g_Pb1[(size_t)BB*SS*SS];    // fp16 unnormalized exp
__device__ unsigned short g_Pb2[(size_t)BB*SS*SS];
__device__ float          g_psum[(size_t)2*NROW*16];  // per-(row, n-tile) sums
__device__ float          g_rinv[2*NROW];             // 1/rowsum (buf0 | buf1)

// ---------------------------------------------------------------------------
// Helpers
// ---------------------------------------------------------------------------
__device__ __forceinline__ uint32_t smem_u32(const void* p) {
    uint32_t a;
    asm("{ .reg .u64 t; cvta.to.shared.u64 t, %1; cvt.u32.u64 %0, t; }"
        : "=r"(a) : "l"(p));
    return a;
}
__device__ __forceinline__ void cp16(uint32_t s, const void* g) {
    asm volatile("cp.async.cg.shared.global [%0], [%1], 16;" :: "r"(s), "l"(g));
}
#define CP_COMMIT() asm volatile("cp.async.commit_group;" ::: "memory")
#define CP_WAIT0()  asm volatile("cp.async.wait_group 0;" ::: "memory")

__device__ __forceinline__ void ldm_x4(uint32_t* r, uint32_t a) {
    asm volatile("ldmatrix.sync.aligned.m8n8.x4.shared.b16 {%0,%1,%2,%3}, [%4];"
        : "=r"(r[0]), "=r"(r[1]), "=r"(r[2]), "=r"(r[3]) : "r"(a));
}
__device__ __forceinline__ void mma_f16(uint32_t* d, const uint32_t* a, const uint32_t* b) {
    asm volatile(
        "mma.sync.aligned.m16n8k16.row.col.f16.f16.f16.f16 "
        "{%0,%1}, {%2,%3,%4,%5}, {%6,%7}, {%0,%1};"
        : "+r"(d[0]), "+r"(d[1])
        : "r"(a[0]), "r"(a[1]), "r"(a[2]), "r"(a[3]), "r"(b[0]), "r"(b[1]));
}
__device__ __forceinline__ unsigned short f2h(float v) {
    return __half_as_ushort(__float2half_rn(v));
}

// ---------------------------------------------------------------------------
// SMEM: 2 stages x (A 128x64 | B 128x64) fp16, row stride 144B.
// 72KB per CTA -> THREE CTAs co-resident per SM.
// ---------------------------------------------------------------------------
#define STAGES     2
#define ROWB       144
#define A_TILE_B   (128 * ROWB)
#define B_TILE_B   (128 * ROWB)
#define STAGE_B    (A_TILE_B + B_TILE_B)      // 36864
#define SMEM_TOTAL (STAGES * STAGE_B)         // 73728

// ---------------------------------------------------------------------------
// Single-pass fp16 TN GEMM (fp16 acc), CTA tile 128x128, 256 thr
// (8 warps 2x4, warp tile 64x32), k-chunk 64, double-buffered, 3 CTAs/SM.
//
// mode 1: Ch[m*ld+n] = f16(acc + bias[n])
// mode 2: Ch[n*ld+m] = f16(acc + bias[n])   (transposed)
// mode 6: Ch[m*ld+n] = f16(exp2(alpha*acc)); also writes per-(row,xtile)
//         partial sums to Cf (psum buffer), deterministic in-CTA reduce.
// mode 8: dual-normalized PV over K-concat [E1|E2]:
//         after first K half, acc *= rinv1[m]/rinv2[m]; epilogue:
//         Cf[m*ld+n] = rinv2[m]*acc + add1? + add2?    (rinv1=bias, rinv2=bias_alt)
// ---------------------------------------------------------------------------
__global__ __launch_bounds__(256, 3) void hmma_tn(
    const unsigned short* __restrict__ A, const unsigned short* __restrict__ Aseg2,
    int KA, const unsigned short* __restrict__ B, int bmask,
    int K, int lda, int ldb, long long a_bs, long long b_bs,
    int zsplit,
    int mode, float alpha, const float* __restrict__ bias,
    float* __restrict__ Cf, unsigned short* __restrict__ Cb,
    long long c_bs, int c_ld,
    const float* __restrict__ add1, const float* __restrict__ add2,
    const unsigned short* __restrict__ A_alt, const unsigned short* __restrict__ B_alt,
    const float* __restrict__ bias_alt, unsigned short* __restrict__ Cb_alt,
    long long cbs_alt, int cld_alt, int mode_alt)
{
    extern __shared__ char smem[];
    const uint32_t sbase = smem_u32(smem);

    const int tid  = threadIdx.x;
    const int wid  = tid >> 5;
    const int lane = tid & 31;
    const int warpM = wid >> 2;      // 0..1 (64 rows each)
    const int warpN = wid & 3;       // 0..3 (32 cols each)
    const int buf = (zsplit > 0 && blockIdx.z >= (unsigned)zsplit) ? 1 : 0;
    int bz = blockIdx.z;
    const int bm = blockIdx.y * 128, bn = blockIdx.x * 128;

    // operand-set select
    const unsigned short* Ab = A;
    const unsigned short* Bb = B;
    const float* biasp = bias;
    unsigned short* Cbp = Cb;
    long long cbs = c_bs;
    int cld = c_ld;
    int md = mode;
    if (buf) {
        bz -= zsplit;
        Ab = A_alt; Bb = B_alt; biasp = bias_alt;
        Cbp = Cb_alt; cbs = cbs_alt; cld = cld_alt; md = mode_alt;
    }

    const unsigned short* gA1 = Ab + bz * a_bs + (long long)bm * lda;
    const unsigned short* gA2 =
        Aseg2 ? Aseg2 + bz * a_bs + (long long)bm * lda : nullptr;
    const unsigned short* gB = Bb + bz * b_bs + (long long)bn * ldb;

    uint32_t acc[4][4][2];
#pragma unroll
    for (int i = 0; i < 4; ++i)
#pragma unroll
        for (int j = 0; j < 4; ++j) { acc[i][j][0] = 0u; acc[i][j][1] = 0u; }

    const int nch = K >> 6;   // k-chunks of 64

    const int lr = tid >> 3, lc = tid & 7;
#define LOAD_CHUNK(c)                                                        \
    do {                                                                     \
        const int koff_ = (c) * 64;                                          \
        const unsigned short* gAc_ = gA1; int ka_ = koff_;                   \
        if (gA2 && koff_ >= KA) { gAc_ = gA2; ka_ = koff_ - KA; }            \
        const int kb_ = koff_ & bmask;                                       \
        const uint32_t sb_ = sbase + ((c) & 1) * STAGE_B;                    \
        _Pragma("unroll")                                                    \
        for (int h_ = 0; h_ < 4; ++h_) {      /* A: 128 rows */              \
            const int row_ = lr + h_ * 32;                                   \
            cp16(sb_ + (uint32_t)(row_ * ROWB + lc * 16),                    \
                 gAc_ + (long long)row_ * lda + ka_ + lc * 8);               \
        }                                                                    \
        _Pragma("unroll")                                                    \
        for (int h_ = 0; h_ < 4; ++h_) {      /* B: 128 rows */              \
            const int row_ = lr + h_ * 32;                                   \
            cp16(sb_ + A_TILE_B + (uint32_t)(row_ * ROWB + lc * 16),         \
                 gB + (long long)row_ * ldb + kb_ + lc * 8);                 \
        }                                                                    \
        CP_COMMIT();                                                         \
    } while (0)

    LOAD_CHUNK(0);

    // ldmatrix geometry
    const int a_row = warpM * 64 + (lane & 15);
    const int a_colb = (lane >> 4) * 16;
    const int b_row = warpN * 32 + (lane & 7) + ((lane >> 4) & 1) * 8;
    const int b_colb = ((lane >> 3) & 1) * 16;
    const int g = lane >> 2;

    const int halfc = nch >> 1;

    for (int c = 0; c < nch; ++c) {
        CP_WAIT0();
        __syncthreads();

        if (c + 1 < nch) LOAD_CHUNK(c + 1);

        // mode 8 midpoint: acc(=S1) *= rinv1[m]/rinv2[m], per accumulator row
        if (md == 8 && c == halfc) {
#pragma unroll
            for (int mi = 0; mi < 4; ++mi)
#pragma unroll
                for (int half = 0; half < 2; ++half) {
                    const long long row = (long long)bz * 2048 + bm
                        + warpM * 64 + mi * 16 + g + half * 8;
                    const float r1 = __ldg(biasp + row);
                    const float r2 = __ldg(bias_alt + row);
                    const __half2 rat = __float2half2_rn(r1 / r2);
#pragma unroll
                    for (int ni = 0; ni < 4; ++ni) {
                        __half2 t = *(__half2*)&acc[mi][ni][half];
                        t = __hmul2(t, rat);
                        acc[mi][ni][half] = *(uint32_t*)&t;
                    }
                }
        }

        const uint32_t tA = sbase + (c & 1) * STAGE_B;
        const uint32_t tB = tA + A_TILE_B;

#pragma unroll
        for (int ks = 0; ks < 4; ++ks) {
            uint32_t af[4][4], bfr[4][2];
#pragma unroll
            for (int mi = 0; mi < 4; ++mi)
                ldm_x4(af[mi], tA + (uint32_t)((a_row + mi * 16) * ROWB
                                               + ks * 32 + a_colb));
#pragma unroll
            for (int p = 0; p < 2; ++p) {
                uint32_t r[4];
                ldm_x4(r, tB + (uint32_t)((b_row + p * 16) * ROWB
                                          + ks * 32 + b_colb));
                bfr[2*p][0] = r[0]; bfr[2*p][1] = r[1];
                bfr[2*p+1][0] = r[2]; bfr[2*p+1][1] = r[3];
            }
#pragma unroll
            for (int mi = 0; mi < 4; ++mi)
#pragma unroll
                for (int ni = 0; ni < 4; ++ni)
                    mma_f16(acc[mi][ni], af[mi], bfr[ni]);
        }
    }
#undef LOAD_CHUNK

    // ------------------------- epilogue (register direct) -------------------
    const int tig = lane & 3;
    const long long c_off = (long long)bz * cbs;

    if (md == 6) {
        // exp epilogue + deterministic per-(row, xtile) partial sums
        float rowpart[4][2] = {{0.f,0.f},{0.f,0.f},{0.f,0.f},{0.f,0.f}};
#pragma unroll
        for (int mi = 0; mi < 4; ++mi) {
#pragma unroll
            for (int ni = 0; ni < 4; ++ni) {
                const int m0 = bm + warpM * 64 + mi * 16 + g;
                const int n0 = bn + warpN * 32 + ni * 8 + tig * 2;
#pragma unroll
                for (int half = 0; half < 2; ++half) {
                    const int m = m0 + half * 8;
                    const __half2 hv = *(const __half2*)&acc[mi][ni][half];
                    const float e0 = exp2f(alpha * __low2float(hv));
                    const float e1 = exp2f(alpha * __high2float(hv));
                    *(ushort2*)&Cbp[c_off + (long long)m * cld + n0] =
                        make_ushort2(f2h(e0), f2h(e1));
                    rowpart[mi][half] += e0 + e1;
                }
            }
        }
        // reduce over the 4 quad lanes (tig = lane bits 0..1)
#pragma unroll
        for (int off = 1; off <= 2; off <<= 1)
#pragma unroll
            for (int mi = 0; mi < 4; ++mi)
#pragma unroll
                for (int half = 0; half < 2; ++half)
                    rowpart[mi][half] +=
                        __shfl_xor_sync(0xffffffffu, rowpart[mi][half], off);

        float* sred = (float*)smem;       // 4 x 128 floats (reuse stage smem)
        __syncthreads();                  // mainloop smem reads complete
        if (tig == 0) {
#pragma unroll
            for (int mi = 0; mi < 4; ++mi)
#pragma unroll
                for (int half = 0; half < 2; ++half)
                    sred[warpN * 128 + warpM * 64 + mi * 16 + g + half * 8] =
                        rowpart[mi][half];
        }
        __syncthreads();
        if (tid < 128) {
            const float s = sred[tid] + sred[128 + tid]
                          + sred[256 + tid] + sred[384 + tid];
            Cf[((long long)buf * NROW + (long long)bz * 2048 + bm + tid) * 16
               + blockIdx.x] = s;
        }
        return;
    }

    // per-row rinv2 for mode 8, hoisted
    float rm[4][2];
    if (md == 8) {
#pragma unroll
        for (int mi = 0; mi < 4; ++mi)
#pragma unroll
            for (int half = 0; half < 2; ++half)
                rm[mi][half] = __ldg(bias_alt + (long long)bz * 2048
                                     + bm + warpM * 64 + mi * 16 + g + half * 8);
    }

#pragma unroll
    for (int mi = 0; mi < 4; ++mi) {
#pragma unroll
        for (int ni = 0; ni < 4; ++ni) {
            const int m0 = bm + warpM * 64 + mi * 16 + g;
            const int n0 = bn + warpN * 32 + ni * 8 + tig * 2;
#pragma unroll
            for (int half = 0; half < 2; ++half) {
                const int m = m0 + half * 8;
                const __half2 hv = *(const __half2*)&acc[mi][ni][half];
                float v0 = __low2float(hv);
                float v1 = __high2float(hv);
                if (md == 1) {
                    v0 += __ldg(biasp + n0);
                    v1 += __ldg(biasp + n0 + 1);
                    *(ushort2*)&Cbp[c_off + (long long)m * cld + n0] =
                        make_ushort2(f2h(v0), f2h(v1));
                } else if (md == 2) {
                    v0 += __ldg(biasp + n0);
                    v1 += __ldg(biasp + n0 + 1);
                    Cbp[c_off + (long long)n0 * cld + m] = f2h(v0);
                    Cbp[c_off + (long long)(n0 + 1) * cld + m] = f2h(v1);
                } else {  // mode 8
                    const float r = rm[mi][half];
                    v0 *= r; v1 *= r;
                    const long long o = c_off + (long long)m * cld + n0;
                    if (add1) { float2 t = *(const float2*)&add1[o]; v0 += t.x; v1 += t.y; }
                    if (add2) { float2 t = *(const float2*)&add2[o]; v0 += t.x; v1 += t.y; }
                    *(float2*)&Cf[o] = make_float2(v0, v1);
                }
            }
        }
    }
}

// ---------------------------------------------------------------------------
// fp32 -> fp16, vectorized: two equal-size arrays in one launch
// ---------------------------------------------------------------------------
__global__ __launch_bounds__(256) void tofp16_dual(
    const float* __restrict__ s1, unsigned short* __restrict__ d1,
    const float* __restrict__ s2, unsigned short* __restrict__ d2, int n)
{
    const int q = n >> 2;
    const int i = blockIdx.x * 256 + threadIdx.x;
    const float* s;
    unsigned short* d;
    int j;
    if (i < q)           { s = s1; d = d1; j = i; }
    else if (i < 2 * q)  { s = s2; d = d2; j = i - q; }
    else return;
    const float4 v = *(const float4*)(s + (size_t)j * 4);
    ushort4 o;
    o.x = f2h(v.x); o.y = f2h(v.y); o.z = f2h(v.z); o.w = f2h(v.w);
    *(ushort4*)(d + (size_t)j * 4) = o;
}

// ---------------------------------------------------------------------------
// rinv[row] = 1 / sum of 16 per-tile partials  (rows = 2*NROW)
// ---------------------------------------------------------------------------
__global__ __launch_bounds__(256) void rinv_from_psum(
    const float* __restrict__ psum, float* __restrict__ rinv)
{
    const int r = blockIdx.x * 256 + threadIdx.x;
    if (r < 2 * NROW) {
        const float4* p = (const float4*)(psum + (size_t)r * 16);
        const float4 a = p[0], b = p[1], c = p[2], d = p[3];
        const float s = a.x + a.y + a.z + a.w + b.x + b.y + b.z + b.w
                      + c.x + c.y + c.z + c.w + d.x + d.y + d.z + d.w;
        rinv[r] = 1.0f / s;
    }
}

// ---------------------------------------------------------------------------
// Launch sequence
// ---------------------------------------------------------------------------
extern "C" void kernel_launch(void* const* d_in, const int* in_sizes, int n_in,
                              void* d_out, int out_size)
{
    (void)in_sizes; (void)n_in; (void)out_size;

    const float* X    = (const float*)d_in[0];
    const float* Y    = (const float*)d_in[1];
    const float* W_xq = (const float*)d_in[2];
    const float* b_xq = (const float*)d_in[3];
    const float* W_yq = (const float*)d_in[4];
    const float* b_yq = (const float*)d_in[5];
    const float* W_fk = (const float*)d_in[6];
    const float* b_fk = (const float*)d_in[7];
    const float* W_fv = (const float*)d_in[8];
    const float* b_fv = (const float*)d_in[9];
    float* out = (float*)d_out;

#define SYM(T, name, gsym) T* name; cudaGetSymbolAddress((void**)&name, gsym)
    SYM(unsigned short, Xb, g_Xb);     SYM(unsigned short, Yb, g_Yb);
    SYM(unsigned short, Wxqb, g_Wxqb); SYM(unsigned short, Wyqb, g_Wyqb);
    SYM(unsigned short, Wfkb, g_Wfkb); SYM(unsigned short, Wfvb, g_Wfvb);
    SYM(unsigned short, Qb, g_Qb);     SYM(unsigned short, Kb, g_Kb);
    SYM(unsigned short, Vtb, g_Vtb);
    SYM(unsigned short, Pb1, g_Pb1);   SYM(unsigned short, Pb2, g_Pb2);
    SYM(float, psum, g_psum);          SYM(float, rinv, g_rinv);
#undef SYM

    cudaFuncSetAttribute(hmma_tn, cudaFuncAttributeMaxDynamicSharedMemorySize, SMEM_TOTAL);

    // alpha for QK: (1/sqrt(512)) * log2(e)
    const float alpha_qk = 0.06375948809f;
    const long long XBS = (long long)SS * DD;
    const long long QBS = (long long)SS * CC;
    const long long PBS = (long long)SS * SS;
    const long long VBS = (long long)DD * SS;

    // ---- fp16 conversions ----
    const int nX = NROW * DD;
    tofp16_dual<<<(2 * (nX / 4)) / 256, 256>>>(X, Xb, Y, Yb, nX);
    tofp16_dual<<<(2 * (DD * DD / 4)) / 256, 256>>>(W_xq, Wxqb, W_yq, Wyqb, DD * DD);
    tofp16_dual<<<(2 * (DD * CC / 4)) / 256, 256>>>(W_fk, Wfkb, W_fv, Wfvb, DD * CC);

    // ---- projections: Q1 (z<8) and Q2 (z>=8) in one launch ----
    hmma_tn<<<dim3(4, 16, 16), 256, SMEM_TOTAL>>>(
        Xb, nullptr, DD, Wxqb, DD - 1,
        DD, DD, DD, XBS, 0, /*zsplit*/8,
        1, 1.f, b_xq, nullptr, Qb, QBS, CC, nullptr, nullptr,
        Yb, Wyqb, b_yq, Qb + DD, QBS, CC, 1);

    // ---- Kf (z<8, mode 1) and Vt (z>=8, mode 2 transposed) ----
    hmma_tn<<<dim3(4, 16, 16), 256, SMEM_TOTAL>>>(
        Qb, nullptr, CC, Wfkb, CC - 1,
        CC, CC, CC, QBS, 0, /*zsplit*/8,
        1, 1.f, b_fk, nullptr, Kb, XBS, DD, nullptr, nullptr,
        Qb, Wfvb, b_fv, Vtb, VBS, SS, 2);

    // ---- QK with fused exp + per-tile row partial sums ----
    hmma_tn<<<dim3(16, 16, 16), 256, SMEM_TOTAL>>>(
        Qb, nullptr, DD, Kb, DD - 1,
        DD, CC, DD, QBS, XBS, /*zsplit*/8,
        6, alpha_qk, nullptr, psum, Pb1, PBS, SS, nullptr, nullptr,
        Qb + DD, Kb, nullptr, Pb2, PBS, SS, 6);

    // ---- rinv from 4MB of partials (deterministic) ----
    rinv_from_psum<<<(2 * NROW + 255) / 256, 256>>>(psum, rinv);

    // ---- single fused PV: out = rinv1[m]*(E1@Vt) + rinv2[m]*(E2@Vt) + X + Y
    hmma_tn<<<dim3(4, 16, 8), 256, SMEM_TOTAL>>>(
        Pb1, Pb2, SS, Vtb, SS - 1,
        2 * SS, SS, SS, PBS, VBS, /*zsplit*/0,
        8, 1.f, rinv, out, nullptr, XBS, DD, X, Y,
        nullptr, nullptr, rinv + NROW, nullptr, 0, 0, 0);
}